// round 11
// baseline (speedup 1.0000x reference)
#include <cuda_runtime.h>
#include <cuda_bf16.h>
#include <cstdint>

#define NODES 100000
#define EDGES 1600000
#define D 32
#define LAYERS 3
#define HOPS 3

#define SCAN_B 512

// ---------------- scratch (device globals) ----------------
__device__ float g_tmp3[NODES * 3];               // [deg | count | fill] one memset
__device__ unsigned long long g_scanstate[256];   // decoupled-lookback state
__device__ int   g_rowptr[NODES + 1];
__device__ __align__(16) int2 g_epack[EDGES];     // (row, __float_as_int(norm)) grouped by col
__device__ float g_P[4 * NODES * D];              // P_k = x @ W[l,k]
__device__ float g_bufS[NODES * D];
__device__ float g_bufG[NODES * D];
__device__ float g_x[NODES * D];

// ---------------- f32x2 helpers ----------------
__device__ __forceinline__ unsigned long long pack2(float a, float b) {
    unsigned long long r;
    asm("mov.b64 %0, {%1, %2};" : "=l"(r) : "f"(a), "f"(b));
    return r;
}
__device__ __forceinline__ float2 unpack2(unsigned long long v) {
    float2 r;
    asm("mov.b64 {%0, %1}, %2;" : "=f"(r.x), "=f"(r.y) : "l"(v));
    return r;
}
__device__ __forceinline__ void fma2(unsigned long long& d,
                                     unsigned long long a, unsigned long long b) {
    asm("fma.rn.f32x2 %0, %1, %2, %0;" : "+l"(d) : "l"(a), "l"(b));
}

// ---------------- setup kernels ----------------

__global__ void deg_kernel(const int* __restrict__ col, const float* __restrict__ ew, int E)
{
    int e = blockIdx.x * blockDim.x + threadIdx.x;
    if (e < E) {
        int c = col[e];
        atomicAdd(&g_tmp3[c], ew[e]);                                  // deg (raw)
        atomicAdd(reinterpret_cast<int*>(g_tmp3 + NODES) + c, 1);      // count
    }
}

// single-pass exclusive scan of count -> rowptr, decoupled lookback across blocks
__global__ void scanfused_kernel(int N, int E)
{
    __shared__ int sh[SCAN_B];
    __shared__ int s_prefix;
    const int* cnt = reinterpret_cast<const int*>(g_tmp3 + NODES);
    int t = threadIdx.x, b = blockIdx.x;
    int i = b * SCAN_B + t;
    int v = (i < N) ? cnt[i] : 0;
    sh[t] = v;
    __syncthreads();
#pragma unroll
    for (int off = 1; off < SCAN_B; off <<= 1) {
        int add = (t >= off) ? sh[t - off] : 0;
        __syncthreads();
        sh[t] += add;
        __syncthreads();
    }
    int incl = sh[t];
    int total = sh[SCAN_B - 1];

    if (t == 0) {
        unsigned long long flag = (b == 0) ? 2ull : 1ull;
        atomicExch(&g_scanstate[b], (flag << 32) | (unsigned)total);
        int prefix = 0;
        if (b > 0) {
            int j = b - 1;
            while (true) {
                unsigned long long s;
                do { s = atomicAdd(&g_scanstate[j], 0ull); } while ((s >> 32) == 0ull);
                prefix += (int)(unsigned)s;
                if ((s >> 32) == 2ull) break;
                j--;
            }
            atomicExch(&g_scanstate[b], (2ull << 32) | (unsigned)(prefix + total));
        }
        s_prefix = prefix;
    }
    __syncthreads();
    if (i < N) g_rowptr[i] = s_prefix + incl - v;
    if (i == N) g_rowptr[N] = E;
}

// scatter edges into CSR slots grouped by col; norm computed inline from raw deg
__global__ void fill_kernel(const int* __restrict__ row, const int* __restrict__ col,
                            const float* __restrict__ ew, int E)
{
    int* fill = reinterpret_cast<int*>(g_tmp3 + 2 * NODES);
    int e = blockIdx.x * blockDim.x + threadIdx.x;
    if (e < E) {
        int r = row[e];
        int c = col[e];
        float dr = g_tmp3[r];
        float dc = g_tmp3[c];
        float sr = (dr > 0.0f) ? rsqrtf(dr) : 0.0f;
        float sc = (dc > 0.0f) ? rsqrtf(dc) : 0.0f;
        float w = sr * ew[e] * sc;
        int p = g_rowptr[c] + atomicAdd(&fill[c], 1);
        g_epack[p] = make_int2(r, __float_as_int(w));
    }
}

// ---------------- multigemm (k-split): P[k][n,:] = x[n,:] @ W4[k] ----------------
// blockIdx.y = k. One 4KB W in smem; 1 node/thread; ~85 regs -> 3 blocks/SM.
__global__ __launch_bounds__(256, 3)
void multigemm_kernel(float* __restrict__ P, const float* __restrict__ x,
                      const float* __restrict__ W4, int N)
{
    __shared__ __align__(16) float Ws[D * D];   // 4 KB
    int t = threadIdx.x;
    int k = blockIdx.y;
    if (t < 256) {
        // 256 float4 = 1024 floats
        reinterpret_cast<float4*>(Ws)[t] =
            reinterpret_cast<const float4*>(W4 + (size_t)k * D * D)[t];
    }
    __syncthreads();

    int n = blockIdx.x * 256 + t;
    if (n >= N) return;

    float h[D];
    const float4* xr = reinterpret_cast<const float4*>(x + (size_t)n * D);
#pragma unroll
    for (int q = 0; q < 8; q++) {
        float4 v = __ldg(xr + q);
        h[q*4] = v.x; h[q*4+1] = v.y; h[q*4+2] = v.z; h[q*4+3] = v.w;
    }

    unsigned long long acc[D / 2];
#pragma unroll
    for (int j = 0; j < D / 2; j++) acc[j] = 0ull;

    const ulonglong2* Wk = reinterpret_cast<const ulonglong2*>(Ws);
#pragma unroll
    for (int i = 0; i < D; i++) {
        unsigned long long hv = pack2(h[i], h[i]);
        const ulonglong2* wr = Wk + i * 8;   // 8 ulonglong2 = 32 floats
#pragma unroll
        for (int j = 0; j < 8; j++) {
            ulonglong2 w = wr[j];
            fma2(acc[j*2],     hv, w.x);
            fma2(acc[j*2 + 1], hv, w.y);
        }
    }

    float* drow = P + (size_t)k * N * D + (size_t)n * D;
#pragma unroll
    for (int j2 = 0; j2 < D / 4; j2++) {
        float2 a = unpack2(acc[j2*2]);
        float2 b = unpack2(acc[j2*2 + 1]);
        reinterpret_cast<float4*>(drow)[j2] = make_float4(a.x, a.y, b.x, b.y);
    }
}

// ---------------- fused hop: dst[n,:] = P[n,:] + sum_e norm_e * h[row_e,:]
// mode 0: plain;  mode 1: + bias then ReLU
__global__ void gather_kernel(float* __restrict__ dst, const float* __restrict__ h,
                              const float* __restrict__ P, const float* __restrict__ bias,
                              int mode, int N)
{
    int gt = blockIdx.x * blockDim.x + threadIdx.x;
    int n = gt >> 5;
    int lane = gt & 31;
    if (n >= N) return;

    int s = g_rowptr[n];
    int e = g_rowptr[n + 1];
    float acc0 = 0.0f, acc1 = 0.0f;

    int i = s;
    if ((i & 1) && i < e) {
        int2 t = g_epack[i];
        acc0 = fmaf(__int_as_float(t.y), __ldg(h + (size_t)t.x * D + lane), acc0);
        i++;
    }
    int npair = (e - i) >> 1;
    const int4* pp = reinterpret_cast<const int4*>(g_epack + i);
#pragma unroll 4
    for (int p = 0; p < npair; p++) {
        int4 t = pp[p];
        float v0 = __ldg(h + (size_t)t.x * D + lane);
        float v1 = __ldg(h + (size_t)t.z * D + lane);
        acc0 = fmaf(__int_as_float(t.y), v0, acc0);
        acc1 = fmaf(__int_as_float(t.w), v1, acc1);
    }
    i += npair * 2;
    if (i < e) {
        int2 t = g_epack[i];
        acc0 = fmaf(__int_as_float(t.y), __ldg(h + (size_t)t.x * D + lane), acc0);
    }

    float v = P[(size_t)n * D + lane] + acc0 + acc1;
    if (mode == 1) v = fmaxf(v + bias[lane], 0.0f);
    dst[(size_t)n * D + lane] = v;
}

// ---------------- launch ----------------

extern "C" void kernel_launch(void* const* d_in, const int* in_sizes, int n_in,
                              void* d_out, int out_size)
{
    const float* x  = (const float*)d_in[0];
    const int*   ei = (const int*)d_in[1];
    const float* ew = (const float*)d_in[2];
    const float* W  = (const float*)d_in[3];
    const float* b  = (const float*)d_in[4];

    const int N = in_sizes[0] / D;
    const int E = in_sizes[2];

    const int* row = ei;
    const int* col = ei + E;

    float* tmp3_p;  cudaGetSymbolAddress((void**)&tmp3_p,  g_tmp3);
    void*  scan_p;  cudaGetSymbolAddress(&scan_p,          g_scanstate);
    float* P_p;     cudaGetSymbolAddress((void**)&P_p,     g_P);
    float* bufS_p;  cudaGetSymbolAddress((void**)&bufS_p,  g_bufS);
    float* bufG_p;  cudaGetSymbolAddress((void**)&bufG_p,  g_bufG);
    float* x_p;     cudaGetSymbolAddress((void**)&x_p,     g_x);

    const int TB = 256;
    const int eb = (E + TB - 1) / TB;
    const int scan_blocks = (N + SCAN_B - 1) / SCAN_B;

    // ---- CSR + norm build ----
    cudaMemsetAsync(tmp3_p, 0, (size_t)3 * N * sizeof(float));
    cudaMemsetAsync(scan_p, 0, 256 * sizeof(unsigned long long));
    deg_kernel<<<eb, TB>>>(col, ew, E);
    scanfused_kernel<<<scan_blocks, SCAN_B>>>(N, E);
    fill_kernel<<<eb, TB>>>(row, col, ew, E);

    const dim3 mg_grid((N + 255) / 256, 4);
    const int gather_blocks = (N * 32 + TB - 1) / TB;
    const size_t ND = (size_t)N * D;

    const float* xcur = x;
    for (int l = 0; l < LAYERS; l++) {
        const float* Wl = W + (size_t)l * (HOPS + 1) * D * D;
        multigemm_kernel<<<mg_grid, 256>>>(P_p, xcur, Wl, N);

        // Horner: x' = relu(P0 + A(P1 + A(P2 + A*P3)) + b)
        gather_kernel<<<gather_blocks, TB>>>(bufS_p, P_p + 3 * ND, P_p + 2 * ND,
                                             nullptr, 0, N);
        gather_kernel<<<gather_blocks, TB>>>(bufG_p, bufS_p, P_p + 1 * ND,
                                             nullptr, 0, N);
        float* dst = (l == LAYERS - 1) ? (float*)d_out : x_p;
        gather_kernel<<<gather_blocks, TB>>>(dst, bufG_p, P_p,
                                             b + (size_t)l * D, 1, N);
        xcur = x_p;
    }
}

// round 12
// speedup vs baseline: 1.1041x; 1.1041x over previous
#include <cuda_runtime.h>
#include <cuda_bf16.h>
#include <cstdint>

#define NODES 100000
#define EDGES 1600000
#define D 32
#define LAYERS 3
#define HOPS 3

#define SCAN_B 512

// ---------------- scratch (device globals) ----------------
__device__ float g_tmp3[NODES * 3];               // [deg | count | fill] one memset
__device__ unsigned long long g_scanstate[256];   // decoupled-lookback state
__device__ int   g_rowptr[NODES + 1];
__device__ __align__(16) int2 g_epack[EDGES];     // (row, __float_as_int(norm)) grouped by col
__device__ float g_g1[NODES * D];
__device__ float g_g2[NODES * D];
__device__ float g_g3[NODES * D];
__device__ float g_x[NODES * D];

// ---------------- f32x2 helpers ----------------
__device__ __forceinline__ unsigned long long pack2(float a, float b) {
    unsigned long long r;
    asm("mov.b64 %0, {%1, %2};" : "=l"(r) : "f"(a), "f"(b));
    return r;
}
__device__ __forceinline__ float2 unpack2(unsigned long long v) {
    float2 r;
    asm("mov.b64 {%0, %1}, %2;" : "=f"(r.x), "=f"(r.y) : "l"(v));
    return r;
}
__device__ __forceinline__ void fma2(unsigned long long& d,
                                     unsigned long long a, unsigned long long b) {
    asm("fma.rn.f32x2 %0, %1, %2, %0;" : "+l"(d) : "l"(a), "l"(b));
}

// ---------------- setup kernels ----------------

__global__ void deg_kernel(const int* __restrict__ col, const float* __restrict__ ew, int E)
{
    int e = blockIdx.x * blockDim.x + threadIdx.x;
    if (e < E) {
        int c = col[e];
        atomicAdd(&g_tmp3[c], ew[e]);                                  // deg (raw)
        atomicAdd(reinterpret_cast<int*>(g_tmp3 + NODES) + c, 1);      // count
    }
}

// single-pass exclusive scan of count -> rowptr, decoupled lookback across blocks
__global__ void scanfused_kernel(int N, int E)
{
    __shared__ int sh[SCAN_B];
    __shared__ int s_prefix;
    const int* cnt = reinterpret_cast<const int*>(g_tmp3 + NODES);
    int t = threadIdx.x, b = blockIdx.x;
    int i = b * SCAN_B + t;
    int v = (i < N) ? cnt[i] : 0;
    sh[t] = v;
    __syncthreads();
#pragma unroll
    for (int off = 1; off < SCAN_B; off <<= 1) {
        int add = (t >= off) ? sh[t - off] : 0;
        __syncthreads();
        sh[t] += add;
        __syncthreads();
    }
    int incl = sh[t];
    int total = sh[SCAN_B - 1];

    if (t == 0) {
        unsigned long long flag = (b == 0) ? 2ull : 1ull;
        atomicExch(&g_scanstate[b], (flag << 32) | (unsigned)total);
        int prefix = 0;
        if (b > 0) {
            int j = b - 1;
            while (true) {
                unsigned long long s;
                do { s = atomicAdd(&g_scanstate[j], 0ull); } while ((s >> 32) == 0ull);
                prefix += (int)(unsigned)s;
                if ((s >> 32) == 2ull) break;
                j--;
            }
            atomicExch(&g_scanstate[b], (2ull << 32) | (unsigned)(prefix + total));
        }
        s_prefix = prefix;
    }
    __syncthreads();
    if (i < N) g_rowptr[i] = s_prefix + incl - v;
    if (i == N) g_rowptr[N] = E;
}

// scatter edges into CSR slots grouped by col; norm computed inline from raw deg
__global__ void fill_kernel(const int* __restrict__ row, const int* __restrict__ col,
                            const float* __restrict__ ew, int E)
{
    int* fill = reinterpret_cast<int*>(g_tmp3 + 2 * NODES);
    int e = blockIdx.x * blockDim.x + threadIdx.x;
    if (e < E) {
        int r = row[e];
        int c = col[e];
        float dr = g_tmp3[r];
        float dc = g_tmp3[c];
        float sr = (dr > 0.0f) ? rsqrtf(dr) : 0.0f;
        float sc = (dc > 0.0f) ? rsqrtf(dc) : 0.0f;
        float w = sr * ew[e] * sc;
        int p = g_rowptr[c] + atomicAdd(&fill[c], 1);
        g_epack[p] = make_int2(r, __float_as_int(w));
    }
}

// ---------------- pure gather: dst[n,:] = sum_e norm_e * h[row_e,:] ----------------
__global__ void gather_kernel(float* __restrict__ dst, const float* __restrict__ h, int N)
{
    int gt = blockIdx.x * blockDim.x + threadIdx.x;
    int n = gt >> 5;
    int lane = gt & 31;
    if (n >= N) return;

    int s = g_rowptr[n];
    int e = g_rowptr[n + 1];
    float acc0 = 0.0f, acc1 = 0.0f;

    int i = s;
    if ((i & 1) && i < e) {
        int2 t = g_epack[i];
        acc0 = fmaf(__int_as_float(t.y), __ldg(h + (size_t)t.x * D + lane), acc0);
        i++;
    }
    int npair = (e - i) >> 1;
    const int4* pp = reinterpret_cast<const int4*>(g_epack + i);
#pragma unroll 8
    for (int p = 0; p < npair; p++) {
        int4 t = pp[p];
        float v0 = __ldg(h + (size_t)t.x * D + lane);
        float v1 = __ldg(h + (size_t)t.z * D + lane);
        acc0 = fmaf(__int_as_float(t.y), v0, acc0);
        acc1 = fmaf(__int_as_float(t.w), v1, acc1);
    }
    i += npair * 2;
    if (i < e) {
        int2 t = g_epack[i];
        acc0 = fmaf(__int_as_float(t.y), __ldg(h + (size_t)t.x * D + lane), acc0);
    }

    dst[(size_t)n * D + lane] = acc0 + acc1;
}

// ---------------- quadgemm: dst[n,:] = relu( sum_m h_m[n,:] @ W4[m]  + bias ) ------
// All 4 W in smem (16 KB); single acc accumulates all four matmuls.
__global__ __launch_bounds__(256, 2)
void quadgemm_kernel(float* __restrict__ dst,
                     const float* __restrict__ h0, const float* __restrict__ h1,
                     const float* __restrict__ h2, const float* __restrict__ h3,
                     const float* __restrict__ W4, const float* __restrict__ bias,
                     int N)
{
    __shared__ __align__(16) float Ws[4 * D * D];   // 16 KB
    __shared__ float Bs[D];
    int t = threadIdx.x;
#pragma unroll
    for (int q = 0; q < 4; q++)
        reinterpret_cast<float4*>(Ws)[q * 256 + t] =
            reinterpret_cast<const float4*>(W4)[q * 256 + t];
    if (t < D) Bs[t] = bias[t];
    __syncthreads();

    int n = blockIdx.x * 256 + t;
    if (n >= N) return;

    unsigned long long acc[D / 2];
#pragma unroll
    for (int j = 0; j < D / 2; j++) acc[j] = 0ull;

    const float* hs[4] = { h0, h1, h2, h3 };

#pragma unroll
    for (int m = 0; m < 4; m++) {
        float h[D];
        const float4* hr = reinterpret_cast<const float4*>(hs[m] + (size_t)n * D);
#pragma unroll
        for (int q = 0; q < 8; q++) {
            float4 v = __ldg(hr + q);
            h[q*4] = v.x; h[q*4+1] = v.y; h[q*4+2] = v.z; h[q*4+3] = v.w;
        }
        const ulonglong2* Wm = reinterpret_cast<const ulonglong2*>(Ws + m * D * D);
#pragma unroll
        for (int i = 0; i < D; i++) {
            unsigned long long hv = pack2(h[i], h[i]);
            const ulonglong2* wr = Wm + i * 8;   // 8 ulonglong2 = 32 floats
#pragma unroll
            for (int j = 0; j < 8; j++) {
                ulonglong2 w = wr[j];
                fma2(acc[j*2],     hv, w.x);
                fma2(acc[j*2 + 1], hv, w.y);
            }
        }
    }

    float* drow = dst + (size_t)n * D;
#pragma unroll
    for (int j2 = 0; j2 < D / 4; j2++) {
        float2 a = unpack2(acc[j2*2]);
        float2 b = unpack2(acc[j2*2 + 1]);
        float4 o;
        o.x = fmaxf(a.x + Bs[j2*4],     0.0f);
        o.y = fmaxf(a.y + Bs[j2*4 + 1], 0.0f);
        o.z = fmaxf(b.x + Bs[j2*4 + 2], 0.0f);
        o.w = fmaxf(b.y + Bs[j2*4 + 3], 0.0f);
        reinterpret_cast<float4*>(drow)[j2] = o;
    }
}

// ---------------- launch ----------------

extern "C" void kernel_launch(void* const* d_in, const int* in_sizes, int n_in,
                              void* d_out, int out_size)
{
    const float* x  = (const float*)d_in[0];
    const int*   ei = (const int*)d_in[1];
    const float* ew = (const float*)d_in[2];
    const float* W  = (const float*)d_in[3];
    const float* b  = (const float*)d_in[4];

    const int N = in_sizes[0] / D;
    const int E = in_sizes[2];

    const int* row = ei;
    const int* col = ei + E;

    float* tmp3_p;  cudaGetSymbolAddress((void**)&tmp3_p,  g_tmp3);
    void*  scan_p;  cudaGetSymbolAddress(&scan_p,          g_scanstate);
    float* g1_p;    cudaGetSymbolAddress((void**)&g1_p,    g_g1);
    float* g2_p;    cudaGetSymbolAddress((void**)&g2_p,    g_g2);
    float* g3_p;    cudaGetSymbolAddress((void**)&g3_p,    g_g3);
    float* x_p;     cudaGetSymbolAddress((void**)&x_p,     g_x);

    const int TB = 256;
    const int eb = (E + TB - 1) / TB;
    const int scan_blocks = (N + SCAN_B - 1) / SCAN_B;

    // ---- CSR + norm build ----
    cudaMemsetAsync(tmp3_p, 0, (size_t)3 * N * sizeof(float));
    cudaMemsetAsync(scan_p, 0, 256 * sizeof(unsigned long long));
    deg_kernel<<<eb, TB>>>(col, ew, E);
    scanfused_kernel<<<scan_blocks, SCAN_B>>>(N, E);
    fill_kernel<<<eb, TB>>>(row, col, ew, E);

    const int qg_blocks     = (N + 255) / 256;
    const int gather_blocks = (N * 32 + TB - 1) / TB;

    const float* xcur = x;
    for (int l = 0; l < LAYERS; l++) {
        const float* Wl = W + (size_t)l * (HOPS + 1) * D * D;

        // power form: g1 = A x, g2 = A g1, g3 = A g2
        gather_kernel<<<gather_blocks, TB>>>(g1_p, xcur, N);
        gather_kernel<<<gather_blocks, TB>>>(g2_p, g1_p, N);
        gather_kernel<<<gather_blocks, TB>>>(g3_p, g2_p, N);

        float* dst = (l == LAYERS - 1) ? (float*)d_out : x_p;
        // x' = relu(x W0 + g1 W1 + g2 W2 + g3 W3 + b)
        quadgemm_kernel<<<qg_blocks, 256>>>(dst, xcur, g1_p, g2_p, g3_p,
                                            Wl, b + (size_t)l * D, N);
        xcur = x_p;
    }
}